// round 13
// baseline (speedup 1.0000x reference)
#include <cuda_runtime.h>
#include <cuda_fp16.h>
#include <math_constants.h>
#include <cstdint>

#define BSZ   2
#define SEQ   2048
#define HID   1024
#define NH    16
#define HD    64

// Scratch: projected Q/K/V as fp16 [b*NH+h][s][d]; fp16-preconverted X and W.
__device__ __half g_q[BSZ * NH * SEQ * HD];
__device__ __half g_k[BSZ * NH * SEQ * HD];
__device__ __half g_v[BSZ * NH * SEQ * HD];
__device__ __half g_xh[BSZ * SEQ * HID];
__device__ __half g_wh[3 * HID * HID];

// ============================================================================
// helpers
// ============================================================================
__device__ __forceinline__ uint32_t smem_u32(const void* p) {
    uint32_t a;
    asm("{ .reg .u64 t; cvta.to.shared.u64 t, %1; cvt.u32.u64 %0, t; }"
        : "=r"(a) : "l"(p));
    return a;
}
__device__ __forceinline__ void cp16(uint32_t s, const void* g) {
    asm volatile("cp.async.cg.shared.global [%0], [%1], 16;" :: "r"(s), "l"(g));
}
__device__ __forceinline__ void cp_commit() {
    asm volatile("cp.async.commit_group;" ::: "memory");
}
__device__ __forceinline__ void cp_wait2() {
    asm volatile("cp.async.wait_group 2;" ::: "memory");
}
__device__ __forceinline__ void cp_wait0() {
    asm volatile("cp.async.wait_group 0;" ::: "memory");
}
__device__ __forceinline__ float ex2(float x) {
    float r;
    asm("ex2.approx.f32 %0, %1;" : "=f"(r) : "f"(x));
    return r;
}
// pack two fp32 into f16x2: lo half = first arg
__device__ __forceinline__ uint32_t packh2(float lo, float hi) {
    uint32_t d;
    asm("cvt.rn.f16x2.f32 %0, %1, %2;" : "=r"(d) : "f"(hi), "f"(lo));
    return d;
}
__device__ __forceinline__ void ldm4(uint32_t* r, uint32_t addr) {
    asm volatile("ldmatrix.sync.aligned.m8n8.x4.shared.b16 {%0,%1,%2,%3}, [%4];"
                 : "=r"(r[0]), "=r"(r[1]), "=r"(r[2]), "=r"(r[3]) : "r"(addr));
}
__device__ __forceinline__ void ldm4t(uint32_t* r, uint32_t addr) {
    asm volatile("ldmatrix.sync.aligned.m8n8.x4.trans.shared.b16 {%0,%1,%2,%3}, [%4];"
                 : "=r"(r[0]), "=r"(r[1]), "=r"(r[2]), "=r"(r[3]) : "r"(addr));
}
__device__ __forceinline__ void mma_f16(float* c, const uint32_t* a,
                                        uint32_t b0, uint32_t b1) {
    asm volatile(
        "mma.sync.aligned.m16n8k16.row.col.f32.f16.f16.f32 "
        "{%0,%1,%2,%3}, {%4,%5,%6,%7}, {%8,%9}, {%0,%1,%2,%3};"
        : "+f"(c[0]), "+f"(c[1]), "+f"(c[2]), "+f"(c[3])
        : "r"(a[0]), "r"(a[1]), "r"(a[2]), "r"(a[3]), "r"(b0), "r"(b1));
}

// ============================================================================
// Pre-pass: fp16-convert X and the three weight matrices.
// ============================================================================
__global__ __launch_bounds__(256) void cvt_kernel(
    const float* __restrict__ X,
    const float* __restrict__ Wq,
    const float* __restrict__ Wk,
    const float* __restrict__ Wv)
{
    const int tid    = blockIdx.x * blockDim.x + threadIdx.x;
    const int stride = gridDim.x * blockDim.x;
    const int NX = BSZ * SEQ * HID / 4;
    uint2* xh = (uint2*)g_xh;
    for (int i = tid; i < NX; i += stride) {
        float4 v = ((const float4*)X)[i];
        xh[i] = make_uint2(packh2(v.x, v.y), packh2(v.z, v.w));
    }
    const int NW = HID * HID / 4;
    uint2* wq = (uint2*)g_wh;
    uint2* wk = (uint2*)(g_wh + HID * HID);
    uint2* wv = (uint2*)(g_wh + 2 * HID * HID);
    for (int i = tid; i < NW; i += stride) {
        float4 a = ((const float4*)Wq)[i];
        wq[i] = make_uint2(packh2(a.x, a.y), packh2(a.z, a.w));
        float4 b = ((const float4*)Wk)[i];
        wk[i] = make_uint2(packh2(b.x, b.y), packh2(b.z, b.w));
        float4 c = ((const float4*)Wv)[i];
        wv[i] = make_uint2(packh2(c.x, c.y), packh2(c.z, c.w));
    }
}

// ============================================================================
// QKV projection, fp16 HMMA (exact R10/R12): CTA tile 128x128, BK=64,
// 3-stage cp.async, 256 thr = 8 warps (4m x 2n), m16n8k16.
// ============================================================================
#define QPITCH   72                           // halves per row (144B)
#define QA_BYTES (128 * QPITCH * 2)           // 18432
#define QSTAGE   (2 * QA_BYTES)               // 36864
#define QSTAGES  3
#define QKV_SMEM (QSTAGES * QSTAGE)           // 110592
#define QNKT     (HID / 64)                   // 16

__global__ __launch_bounds__(256) void qkv_mma_kernel(
    const float* __restrict__ bq,
    const float* __restrict__ bk,
    const float* __restrict__ bv)
{
    const float* bias; __half* out;
    if (blockIdx.z == 0)      { bias = bq; out = g_q; }
    else if (blockIdx.z == 1) { bias = bk; out = g_k; }
    else                      { bias = bv; out = g_v; }
    const __half* W = g_wh + (size_t)blockIdx.z * HID * HID;

    extern __shared__ char smem[];
    const uint32_t sb = smem_u32(smem);

    const int tid  = threadIdx.x;
    const int wid  = tid >> 5;
    const int lane = tid & 31;
    const int wm   = wid >> 1;
    const int wn   = wid & 1;
    const int m0   = blockIdx.x * 128;
    const int n0   = blockIdx.y * 128;

    const __half* gA0 = g_xh + (size_t)m0 * HID;
    const __half* gB0 = W + (size_t)n0 * HID;

    auto load_stage = [&](int stage, int kt) {
        const uint32_t sA = sb + stage * QSTAGE;
        const uint32_t sB = sA + QA_BYTES;
        const __half* gA = gA0 + kt * 64;
        const __half* gB = gB0 + kt * 64;
        #pragma unroll
        for (int i = 0; i < 4; i++) {
            int cid = tid + (i << 8);         // 0..1023
            int row = cid >> 3;               // 0..127
            int c   = cid & 7;                // 16B chunk in 128B row
            uint32_t off = row * 144 + c * 16;
            cp16(sA + off, gA + row * HID + c * 8);
            cp16(sB + off, gB + row * HID + c * 8);
        }
    };

    load_stage(0, 0); cp_commit();
    load_stage(1, 1); cp_commit();
    load_stage(2, 2); cp_commit();

    float acc[2][8][4];
    #pragma unroll
    for (int mt = 0; mt < 2; mt++)
        #pragma unroll
        for (int nt = 0; nt < 8; nt++)
            acc[mt][nt][0] = acc[mt][nt][1] = acc[mt][nt][2] = acc[mt][nt][3] = 0.f;

    const int a_row = lane & 15;
    const int a_co  = (lane >> 4) * 16;
    const int b_row = (lane & 7) + ((lane >> 4) << 3);
    const int b_co  = ((lane >> 3) & 1) * 16;

    for (int kt = 0; kt < QNKT; kt++) {
        cp_wait2();
        __syncthreads();
        const uint32_t sA = sb + (kt % QSTAGES) * QSTAGE;
        const uint32_t sB = sA + QA_BYTES;

        #pragma unroll
        for (int kk = 0; kk < 4; kk++) {      // 4 x k16 = BK 64
            uint32_t af[2][4];
            #pragma unroll
            for (int mt = 0; mt < 2; mt++)
                ldm4(af[mt], sA + (wm * 32 + mt * 16 + a_row) * 144 + kk * 32 + a_co);
            #pragma unroll
            for (int np = 0; np < 4; np++) {
                uint32_t bf[4];
                ldm4(bf, sB + (wn * 64 + np * 16 + b_row) * 144 + kk * 32 + b_co);
                #pragma unroll
                for (int mt = 0; mt < 2; mt++) {
                    mma_f16(acc[mt][2 * np],     af[mt], bf[0], bf[1]);
                    mma_f16(acc[mt][2 * np + 1], af[mt], bf[2], bf[3]);
                }
            }
        }
        __syncthreads();
        if (kt + 3 < QNKT) load_stage(kt % QSTAGES, kt + 3);
        cp_commit();
    }

    const int n0g = n0 + wn * 64;
    const int h   = n0g >> 6;
    const int q2  = (lane & 3) * 2;
    #pragma unroll
    for (int mt = 0; mt < 2; mt++) {
        #pragma unroll
        for (int rh = 0; rh < 2; rh++) {
            int mrow = m0 + wm * 32 + mt * 16 + (lane >> 2) + rh * 8;
            int b = mrow >> 11;
            int s = mrow & (SEQ - 1);
            __half* op = out + (((size_t)(b * NH + h) * SEQ + s) * HD);
            #pragma unroll
            for (int nt = 0; nt < 8; nt++) {
                int d = nt * 8 + q2;
                float2 bb = *(const float2*)&bias[n0g + d];
                __half2 hv = __floats2half2_rn(acc[mt][nt][rh * 2 + 0] + bb.x,
                                               acc[mt][nt][rh * 2 + 1] + bb.y);
                *(__half2*)&op[d] = hv;
            }
        }
    }
}

// ============================================================================
// Flash attention v8: CTA = 128 queries, 8 warps x 16 q (warp code identical
// to R12). K/V/mask shared by 8 warps -> half the global/cp.async traffic.
// __launch_bounds__(256, 2): 2 CTAs/SM = 16 warps (same as R12's 4x128).
// ============================================================================
#define HPITCH   72
#define HTILE_B  (64 * HPITCH * 2)            // 9216 bytes (64-row tile)
#define QTILE_B  (128 * HPITCH * 2)           // 18432 bytes (128-row Q tile)
#define NKT      (SEQ / 64)
#define ATT_SMEM (QTILE_B + 4 * HTILE_B + 512)
#define SCALE2   0.18033688f                  // 0.125 * log2(e)

__global__ __launch_bounds__(256, 2) void attn_mma_kernel(
    const int* __restrict__ mask, float* __restrict__ out)
{
    extern __shared__ char smc[];
    const uint32_t sQ  = smem_u32(smc);
    const uint32_t sKb = sQ + QTILE_B;
    const uint32_t sVb = sKb + 2 * HTILE_B;
    const uint32_t sM  = sVb + 2 * HTILE_B;
    int* mskb = (int*)(smc + QTILE_B + 4 * HTILE_B);

    const int tid  = threadIdx.x;
    const int lane = tid & 31;
    const int w    = tid >> 5;                 // 0..7 -> q rows 16w..16w+15
    const int s0   = blockIdx.x * 128;
    const int bh   = blockIdx.y;
    const int b    = bh >> 4;

    const int q2 = (lane & 3) * 2;
    const int r0 = lane >> 2;

    const int a_row = lane & 15;
    const int a_co  = (lane >> 4) * 16;
    const int b_row = (lane & 7) + ((lane >> 4) << 3);
    const int b_co  = ((lane >> 3) & 1) * 16;
    const int v_row = lane & 15;
    const int v_co  = (lane >> 4) * 16;

    // ---- prologue: Q(128 rows) + K(0) + V(0) + mask(0) via cp.async ----
    {
        const __half* Qg = g_q + (size_t)(bh * SEQ + s0) * HD;
        const __half* Kg = g_k + (size_t)bh * SEQ * HD;
        const __half* Vg = g_v + (size_t)bh * SEQ * HD;
        #pragma unroll
        for (int i = 0; i < 4; i++) {          // Q: 1024 chunks / 256 thr
            int cid = tid + (i << 8);
            int row = cid >> 3;                // 0..127
            int c   = cid & 7;
            cp16(sQ + row * 144 + c * 16, Qg + row * HD + c * 8);
        }
        #pragma unroll
        for (int i = 0; i < 2; i++) {          // K,V: 512 chunks / 256 thr
            int cid = tid + (i << 8);
            int row = cid >> 3;                // 0..63
            int c   = cid & 7;
            uint32_t off = row * 144 + c * 16;
            cp16(sKb + off, Kg + row * HD + c * 8);
            cp16(sVb + off, Vg + row * HD + c * 8);
        }
        if (tid < 16) cp16(sM + tid * 16, mask + b * SEQ + tid * 4);
        cp_commit();
        cp_wait0();
    }
    __syncthreads();

    float mI0 = -CUDART_INF_F, mI1 = -CUDART_INF_F, l0 = 0.f, l1 = 0.f;
    float o[8][4];
    #pragma unroll
    for (int dt = 0; dt < 8; dt++)
        o[dt][0] = o[dt][1] = o[dt][2] = o[dt][3] = 0.f;

    for (int kt = 0; kt < NKT; kt++) {
        const int cur = kt & 1;
        const bool has_next = (kt + 1 < NKT);

        if (has_next) {
            const __half* Kg = g_k + (size_t)(bh * SEQ + (kt + 1) * 64) * HD;
            const __half* Vg = g_v + (size_t)(bh * SEQ + (kt + 1) * 64) * HD;
            const uint32_t sKn = sKb + (cur ^ 1) * HTILE_B;
            const uint32_t sVn = sVb + (cur ^ 1) * HTILE_B;
            #pragma unroll
            for (int i = 0; i < 2; i++) {
                int cid = tid + (i << 8);
                int row = cid >> 3;
                int c   = cid & 7;
                uint32_t off = row * 144 + c * 16;
                cp16(sKn + off, Kg + row * HD + c * 8);
                cp16(sVn + off, Vg + row * HD + c * 8);
            }
            if (tid < 16)
                cp16(sM + (cur ^ 1) * 256 + tid * 16,
                     mask + b * SEQ + (kt + 1) * 64 + tid * 4);
            cp_commit();
        }

        // ---- S = Q K^T ----
        const uint32_t sKc = sKb + cur * HTILE_B;
        float s[8][4];
        #pragma unroll
        for (int nt = 0; nt < 8; nt++)
            s[nt][0] = s[nt][1] = s[nt][2] = s[nt][3] = 0.f;
        #pragma unroll
        for (int kk = 0; kk < 4; kk++) {
            uint32_t aq[4];
            ldm4(aq, sQ + (16 * w + a_row) * 144 + kk * 32 + a_co);
            #pragma unroll
            for (int np = 0; np < 4; np++) {
                uint32_t bf[4];
                ldm4(bf, sKc + (np * 16 + b_row) * 144 + kk * 32 + b_co);
                mma_f16(s[2 * np],     aq, bf[0], bf[1]);
                mma_f16(s[2 * np + 1], aq, bf[2], bf[3]);
            }
        }

        // ---- scale + mask + online softmax (exp2 domain) ----
        const int* mk = mskb + cur * 64;
        float mx0 = -CUDART_INF_F, mx1 = -CUDART_INF_F;
        #pragma unroll
        for (int nt = 0; nt < 8; nt++) {
            float f0 = mk[nt * 8 + q2]     ? 0.f : -CUDART_INF_F;
            float f1 = mk[nt * 8 + q2 + 1] ? 0.f : -CUDART_INF_F;
            s[nt][0] = s[nt][0] * SCALE2 + f0;
            s[nt][1] = s[nt][1] * SCALE2 + f1;
            s[nt][2] = s[nt][2] * SCALE2 + f0;
            s[nt][3] = s[nt][3] * SCALE2 + f1;
            mx0 = fmaxf(mx0, fmaxf(s[nt][0], s[nt][1]));
            mx1 = fmaxf(mx1, fmaxf(s[nt][2], s[nt][3]));
        }
        mx0 = fmaxf(mx0, __shfl_xor_sync(0xffffffffu, mx0, 1));
        mx0 = fmaxf(mx0, __shfl_xor_sync(0xffffffffu, mx0, 2));
        mx1 = fmaxf(mx1, __shfl_xor_sync(0xffffffffu, mx1, 1));
        mx1 = fmaxf(mx1, __shfl_xor_sync(0xffffffffu, mx1, 2));

        float mn0 = fmaxf(mI0, mx0), mn1 = fmaxf(mI1, mx1);
        float mu0 = (mn0 == -CUDART_INF_F) ? 0.f : mn0;
        float mu1 = (mn1 == -CUDART_INF_F) ? 0.f : mn1;
        float al0 = ex2(mI0 - mu0), al1 = ex2(mI1 - mu1);
        float rs0 = 0.f, rs1 = 0.f;
        #pragma unroll
        for (int nt = 0; nt < 8; nt++) {
            s[nt][0] = ex2(s[nt][0] - mu0);
            s[nt][1] = ex2(s[nt][1] - mu0);
            s[nt][2] = ex2(s[nt][2] - mu1);
            s[nt][3] = ex2(s[nt][3] - mu1);
            rs0 += s[nt][0] + s[nt][1];
            rs1 += s[nt][2] + s[nt][3];
        }
        rs0 += __shfl_xor_sync(0xffffffffu, rs0, 1);
        rs0 += __shfl_xor_sync(0xffffffffu, rs0, 2);
        rs1 += __shfl_xor_sync(0xffffffffu, rs1, 1);
        rs1 += __shfl_xor_sync(0xffffffffu, rs1, 2);
        l0 = l0 * al0 + rs0; mI0 = mn0;
        l1 = l1 * al1 + rs1; mI1 = mn1;
        #pragma unroll
        for (int dt = 0; dt < 8; dt++) {
            o[dt][0] *= al0; o[dt][1] *= al0;
            o[dt][2] *= al1; o[dt][3] *= al1;
        }

        // ---- O += P V ----
        const uint32_t sVc = sVb + cur * HTILE_B;
        #pragma unroll
        for (int kp = 0; kp < 4; kp++) {
            uint32_t pa[4];
            pa[0] = packh2(s[2 * kp][0],     s[2 * kp][1]);
            pa[1] = packh2(s[2 * kp][2],     s[2 * kp][3]);
            pa[2] = packh2(s[2 * kp + 1][0], s[2 * kp + 1][1]);
            pa[3] = packh2(s[2 * kp + 1][2], s[2 * kp + 1][3]);
            #pragma unroll
            for (int np = 0; np < 4; np++) {
                uint32_t vf[4];
                ldm4t(vf, sVc + (16 * kp + v_row) * 144 + np * 32 + v_co);
                mma_f16(o[2 * np],     pa, vf[0], vf[1]);
                mma_f16(o[2 * np + 1], pa, vf[2], vf[3]);
            }
        }

        cp_wait0();
        __syncthreads();
    }

    // ---- epilogue ----
    float inv0 = 1.0f / fmaxf(l0, 1e-30f);
    float inv1 = 1.0f / fmaxf(l1, 1e-30f);
    const int h = bh & 15;
    const int row0 = s0 + 16 * w + r0;
    float* op0 = out + (size_t)(b * SEQ + row0) * HID + h * HD;
    float* op1 = out + (size_t)(b * SEQ + row0 + 8) * HID + h * HD;
    #pragma unroll
    for (int dt = 0; dt < 8; dt++) {
        int d = dt * 8 + q2;
        *(float2*)&op0[d] = make_float2(o[dt][0] * inv0, o[dt][1] * inv0);
        *(float2*)&op1[d] = make_float2(o[dt][2] * inv1, o[dt][3] * inv1);
    }
}

// ---------------------------------------------------------------------------
extern "C" void kernel_launch(void* const* d_in, const int* in_sizes, int n_in,
                              void* d_out, int out_size)
{
    const float* X    = (const float*)d_in[0];
    const int*   mask = (const int*)d_in[1];
    const float* Wq   = (const float*)d_in[2];
    const float* bq   = (const float*)d_in[3];
    const float* Wk   = (const float*)d_in[4];
    const float* bk   = (const float*)d_in[5];
    const float* Wv   = (const float*)d_in[6];
    const float* bv   = (const float*)d_in[7];
    float* out = (float*)d_out;

    cvt_kernel<<<592, 256>>>(X, Wq, Wk, Wv);

    cudaFuncSetAttribute(qkv_mma_kernel,
                         cudaFuncAttributeMaxDynamicSharedMemorySize, QKV_SMEM);
    qkv_mma_kernel<<<dim3(32, 8, 3), 256, QKV_SMEM>>>(bq, bk, bv);

    cudaFuncSetAttribute(attn_mma_kernel,
                         cudaFuncAttributeMaxDynamicSharedMemorySize, ATT_SMEM);
    attn_mma_kernel<<<dim3(SEQ / 128, BSZ * NH), 256, ATT_SMEM>>>(mask, out);
}

// round 14
// speedup vs baseline: 1.6959x; 1.6959x over previous
#include <cuda_runtime.h>
#include <cuda_fp16.h>
#include <math_constants.h>
#include <cstdint>

#define BSZ   2
#define SEQ   2048
#define HID   1024
#define NH    16
#define HD    64

// Scratch: projected Q/K/V as fp16 [b*NH+h][s][d]; fp16-preconverted X and W.
__device__ __half g_q[BSZ * NH * SEQ * HD];
__device__ __half g_k[BSZ * NH * SEQ * HD];
__device__ __half g_v[BSZ * NH * SEQ * HD];
__device__ __half g_xh[BSZ * SEQ * HID];
__device__ __half g_wh[3 * HID * HID];

// ============================================================================
// helpers
// ============================================================================
__device__ __forceinline__ uint32_t smem_u32(const void* p) {
    uint32_t a;
    asm("{ .reg .u64 t; cvta.to.shared.u64 t, %1; cvt.u32.u64 %0, t; }"
        : "=r"(a) : "l"(p));
    return a;
}
__device__ __forceinline__ void cp16(uint32_t s, const void* g) {
    asm volatile("cp.async.cg.shared.global [%0], [%1], 16;" :: "r"(s), "l"(g));
}
__device__ __forceinline__ void cp_commit() {
    asm volatile("cp.async.commit_group;" ::: "memory");
}
__device__ __forceinline__ void cp_wait1() {
    asm volatile("cp.async.wait_group 1;" ::: "memory");
}
__device__ __forceinline__ void cp_wait0() {
    asm volatile("cp.async.wait_group 0;" ::: "memory");
}
__device__ __forceinline__ float ex2(float x) {
    float r;
    asm("ex2.approx.f32 %0, %1;" : "=f"(r) : "f"(x));
    return r;
}
// pack two fp32 into f16x2: lo half = first arg
__device__ __forceinline__ uint32_t packh2(float lo, float hi) {
    uint32_t d;
    asm("cvt.rn.f16x2.f32 %0, %1, %2;" : "=r"(d) : "f"(hi), "f"(lo));
    return d;
}
__device__ __forceinline__ void ldm4(uint32_t* r, uint32_t addr) {
    asm volatile("ldmatrix.sync.aligned.m8n8.x4.shared.b16 {%0,%1,%2,%3}, [%4];"
                 : "=r"(r[0]), "=r"(r[1]), "=r"(r[2]), "=r"(r[3]) : "r"(addr));
}
__device__ __forceinline__ void ldm4t(uint32_t* r, uint32_t addr) {
    asm volatile("ldmatrix.sync.aligned.m8n8.x4.trans.shared.b16 {%0,%1,%2,%3}, [%4];"
                 : "=r"(r[0]), "=r"(r[1]), "=r"(r[2]), "=r"(r[3]) : "r"(addr));
}
__device__ __forceinline__ void mma_f16(float* c, const uint32_t* a,
                                        uint32_t b0, uint32_t b1) {
    asm volatile(
        "mma.sync.aligned.m16n8k16.row.col.f32.f16.f16.f32 "
        "{%0,%1,%2,%3}, {%4,%5,%6,%7}, {%8,%9}, {%0,%1,%2,%3};"
        : "+f"(c[0]), "+f"(c[1]), "+f"(c[2]), "+f"(c[3])
        : "r"(a[0]), "r"(a[1]), "r"(a[2]), "r"(a[3]), "r"(b0), "r"(b1));
}

// ============================================================================
// Pre-pass: fp16-convert X and the three weight matrices.
// ============================================================================
__global__ __launch_bounds__(256) void cvt_kernel(
    const float* __restrict__ X,
    const float* __restrict__ Wq,
    const float* __restrict__ Wk,
    const float* __restrict__ Wv)
{
    const int tid    = blockIdx.x * blockDim.x + threadIdx.x;
    const int stride = gridDim.x * blockDim.x;
    const int NX = BSZ * SEQ * HID / 4;
    uint2* xh = (uint2*)g_xh;
    for (int i = tid; i < NX; i += stride) {
        float4 v = ((const float4*)X)[i];
        xh[i] = make_uint2(packh2(v.x, v.y), packh2(v.z, v.w));
    }
    const int NW = HID * HID / 4;
    uint2* wq = (uint2*)g_wh;
    uint2* wk = (uint2*)(g_wh + HID * HID);
    uint2* wv = (uint2*)(g_wh + 2 * HID * HID);
    for (int i = tid; i < NW; i += stride) {
        float4 a = ((const float4*)Wq)[i];
        wq[i] = make_uint2(packh2(a.x, a.y), packh2(a.z, a.w));
        float4 b = ((const float4*)Wk)[i];
        wk[i] = make_uint2(packh2(b.x, b.y), packh2(b.z, b.w));
        float4 c = ((const float4*)Wv)[i];
        wv[i] = make_uint2(packh2(c.x, c.y), packh2(c.z, c.w));
    }
}

// ============================================================================
// QKV projection, fp16 HMMA: CTA tile 128x128, BK=64, m16n8k16.
// 3 physical stages, 2 loads in flight, ONE barrier per iteration:
//   wait(load kt) -> sync (publishes kt, frees stage kt-1) -> issue kt+2
//   -> compute kt.
// ============================================================================
#define QPITCH   72                           // halves per row (144B)
#define QA_BYTES (128 * QPITCH * 2)           // 18432
#define QSTAGE   (2 * QA_BYTES)               // 36864
#define QSTAGES  3
#define QKV_SMEM (QSTAGES * QSTAGE)           // 110592
#define QNKT     (HID / 64)                   // 16

__global__ __launch_bounds__(256) void qkv_mma_kernel(
    const float* __restrict__ bq,
    const float* __restrict__ bk,
    const float* __restrict__ bv)
{
    const float* bias; __half* out;
    if (blockIdx.z == 0)      { bias = bq; out = g_q; }
    else if (blockIdx.z == 1) { bias = bk; out = g_k; }
    else                      { bias = bv; out = g_v; }
    const __half* W = g_wh + (size_t)blockIdx.z * HID * HID;

    extern __shared__ char smem[];
    const uint32_t sb = smem_u32(smem);

    const int tid  = threadIdx.x;
    const int wid  = tid >> 5;
    const int lane = tid & 31;
    const int wm   = wid >> 1;
    const int wn   = wid & 1;
    const int m0   = blockIdx.x * 128;
    const int n0   = blockIdx.y * 128;

    const __half* gA0 = g_xh + (size_t)m0 * HID;
    const __half* gB0 = W + (size_t)n0 * HID;

    auto load_stage = [&](int stage, int kt) {
        const uint32_t sA = sb + stage * QSTAGE;
        const uint32_t sB = sA + QA_BYTES;
        const __half* gA = gA0 + kt * 64;
        const __half* gB = gB0 + kt * 64;
        #pragma unroll
        for (int i = 0; i < 4; i++) {
            int cid = tid + (i << 8);         // 0..1023
            int row = cid >> 3;               // 0..127
            int c   = cid & 7;                // 16B chunk in 128B row
            uint32_t off = row * 144 + c * 16;
            cp16(sA + off, gA + row * HID + c * 8);
            cp16(sB + off, gB + row * HID + c * 8);
        }
    };

    load_stage(0, 0); cp_commit();
    load_stage(1, 1); cp_commit();

    float acc[2][8][4];
    #pragma unroll
    for (int mt = 0; mt < 2; mt++)
        #pragma unroll
        for (int nt = 0; nt < 8; nt++)
            acc[mt][nt][0] = acc[mt][nt][1] = acc[mt][nt][2] = acc[mt][nt][3] = 0.f;

    const int a_row = lane & 15;
    const int a_co  = (lane >> 4) * 16;
    const int b_row = (lane & 7) + ((lane >> 4) << 3);
    const int b_co  = ((lane >> 3) & 1) * 16;

    for (int kt = 0; kt < QNKT; kt++) {
        cp_wait1();                           // load kt complete
        __syncthreads();                      // publish kt; stage (kt-1)%3 free
        if (kt + 2 < QNKT) {
            load_stage((kt + 2) % QSTAGES, kt + 2);
            cp_commit();
        }

        const uint32_t sA = sb + (kt % QSTAGES) * QSTAGE;
        const uint32_t sB = sA + QA_BYTES;

        #pragma unroll
        for (int kk = 0; kk < 4; kk++) {      // 4 x k16 = BK 64
            uint32_t af[2][4];
            #pragma unroll
            for (int mt = 0; mt < 2; mt++)
                ldm4(af[mt], sA + (wm * 32 + mt * 16 + a_row) * 144 + kk * 32 + a_co);
            #pragma unroll
            for (int np = 0; np < 4; np++) {
                uint32_t bf[4];
                ldm4(bf, sB + (wn * 64 + np * 16 + b_row) * 144 + kk * 32 + b_co);
                #pragma unroll
                for (int mt = 0; mt < 2; mt++) {
                    mma_f16(acc[mt][2 * np],     af[mt], bf[0], bf[1]);
                    mma_f16(acc[mt][2 * np + 1], af[mt], bf[2], bf[3]);
                }
            }
        }
    }

    const int n0g = n0 + wn * 64;
    const int h   = n0g >> 6;
    const int q2  = (lane & 3) * 2;
    #pragma unroll
    for (int mt = 0; mt < 2; mt++) {
        #pragma unroll
        for (int rh = 0; rh < 2; rh++) {
            int mrow = m0 + wm * 32 + mt * 16 + (lane >> 2) + rh * 8;
            int b = mrow >> 11;
            int s = mrow & (SEQ - 1);
            __half* op = out + (((size_t)(b * NH + h) * SEQ + s) * HD);
            #pragma unroll
            for (int nt = 0; nt < 8; nt++) {
                int d = nt * 8 + q2;
                float2 bb = *(const float2*)&bias[n0g + d];
                __half2 hv = __floats2half2_rn(acc[mt][nt][rh * 2 + 0] + bb.x,
                                               acc[mt][nt][rh * 2 + 1] + bb.y);
                *(__half2*)&op[d] = hv;
            }
        }
    }
}

// ============================================================================
// Flash attention (EXACT R12): 64 q/CTA, 4 warps x 16 q, grid 1024,
// __launch_bounds__(128, 4), fp16 m16n8k16, exp2 softmax, P = packed C-frags.
// ============================================================================
#define HPITCH   72
#define HTILE_B  (64 * HPITCH * 2)            // 9216 bytes
#define NKT      (SEQ / 64)
#define ATT_SMEM (5 * HTILE_B + 512)
#define SCALE2   0.18033688f                  // 0.125 * log2(e)

__global__ __launch_bounds__(128, 4) void attn_mma_kernel(
    const int* __restrict__ mask, float* __restrict__ out)
{
    extern __shared__ char smc[];
    const uint32_t sQ  = smem_u32(smc);
    const uint32_t sKb = sQ + HTILE_B;
    const uint32_t sVb = sQ + 3 * HTILE_B;
    const uint32_t sM  = sQ + 5 * HTILE_B;
    int* mskb = (int*)(smc + 5 * HTILE_B);

    const int tid  = threadIdx.x;
    const int lane = tid & 31;
    const int w    = tid >> 5;
    const int s0   = blockIdx.x * 64;
    const int bh   = blockIdx.y;
    const int b    = bh >> 4;

    const int q2 = (lane & 3) * 2;
    const int r0 = lane >> 2;

    const int a_row = lane & 15;
    const int a_co  = (lane >> 4) * 16;
    const int b_row = (lane & 7) + ((lane >> 4) << 3);
    const int b_co  = ((lane >> 3) & 1) * 16;
    const int v_row = lane & 15;
    const int v_co  = (lane >> 4) * 16;

    // ---- prologue ----
    {
        const __half* Qg = g_q + (size_t)(bh * SEQ + s0) * HD;
        const __half* Kg = g_k + (size_t)bh * SEQ * HD;
        const __half* Vg = g_v + (size_t)bh * SEQ * HD;
        #pragma unroll
        for (int i = 0; i < 4; i++) {
            int cid = tid + (i << 7);
            int row = cid >> 3;
            int c   = cid & 7;
            uint32_t off = row * 144 + c * 16;
            cp16(sQ  + off, Qg + row * HD + c * 8);
            cp16(sKb + off, Kg + row * HD + c * 8);
            cp16(sVb + off, Vg + row * HD + c * 8);
        }
        if (tid < 16) cp16(sM + tid * 16, mask + b * SEQ + tid * 4);
        cp_commit();
        cp_wait0();
    }
    __syncthreads();

    float mI0 = -CUDART_INF_F, mI1 = -CUDART_INF_F, l0 = 0.f, l1 = 0.f;
    float o[8][4];
    #pragma unroll
    for (int dt = 0; dt < 8; dt++)
        o[dt][0] = o[dt][1] = o[dt][2] = o[dt][3] = 0.f;

    for (int kt = 0; kt < NKT; kt++) {
        const int cur = kt & 1;
        const bool has_next = (kt + 1 < NKT);

        if (has_next) {
            const __half* Kg = g_k + (size_t)(bh * SEQ + (kt + 1) * 64) * HD;
            const __half* Vg = g_v + (size_t)(bh * SEQ + (kt + 1) * 64) * HD;
            const uint32_t sKn = sKb + (cur ^ 1) * HTILE_B;
            const uint32_t sVn = sVb + (cur ^ 1) * HTILE_B;
            #pragma unroll
            for (int i = 0; i < 4; i++) {
                int cid = tid + (i << 7);
                int row = cid >> 3;
                int c   = cid & 7;
                uint32_t off = row * 144 + c * 16;
                cp16(sKn + off, Kg + row * HD + c * 8);
                cp16(sVn + off, Vg + row * HD + c * 8);
            }
            if (tid < 16)
                cp16(sM + (cur ^ 1) * 256 + tid * 16,
                     mask + b * SEQ + (kt + 1) * 64 + tid * 4);
            cp_commit();
        }

        // ---- S = Q K^T ----
        const uint32_t sKc = sKb + cur * HTILE_B;
        float s[8][4];
        #pragma unroll
        for (int nt = 0; nt < 8; nt++)
            s[nt][0] = s[nt][1] = s[nt][2] = s[nt][3] = 0.f;
        #pragma unroll
        for (int kk = 0; kk < 4; kk++) {
            uint32_t aq[4];
            ldm4(aq, sQ + (16 * w + a_row) * 144 + kk * 32 + a_co);
            #pragma unroll
            for (int np = 0; np < 4; np++) {
                uint32_t bf[4];
                ldm4(bf, sKc + (np * 16 + b_row) * 144 + kk * 32 + b_co);
                mma_f16(s[2 * np],     aq, bf[0], bf[1]);
                mma_f16(s[2 * np + 1], aq, bf[2], bf[3]);
            }
        }

        // ---- scale + mask + online softmax (exp2 domain) ----
        const int* mk = mskb + cur * 64;
        float mx0 = -CUDART_INF_F, mx1 = -CUDART_INF_F;
        #pragma unroll
        for (int nt = 0; nt < 8; nt++) {
            float f0 = mk[nt * 8 + q2]     ? 0.f : -CUDART_INF_F;
            float f1 = mk[nt * 8 + q2 + 1] ? 0.f : -CUDART_INF_F;
            s[nt][0] = s[nt][0] * SCALE2 + f0;
            s[nt][1] = s[nt][1] * SCALE2 + f1;
            s[nt][2] = s[nt][2] * SCALE2 + f0;
            s[nt][3] = s[nt][3] * SCALE2 + f1;
            mx0 = fmaxf(mx0, fmaxf(s[nt][0], s[nt][1]));
            mx1 = fmaxf(mx1, fmaxf(s[nt][2], s[nt][3]));
        }
        mx0 = fmaxf(mx0, __shfl_xor_sync(0xffffffffu, mx0, 1));
        mx0 = fmaxf(mx0, __shfl_xor_sync(0xffffffffu, mx0, 2));
        mx1 = fmaxf(mx1, __shfl_xor_sync(0xffffffffu, mx1, 1));
        mx1 = fmaxf(mx1, __shfl_xor_sync(0xffffffffu, mx1, 2));

        float mn0 = fmaxf(mI0, mx0), mn1 = fmaxf(mI1, mx1);
        float mu0 = (mn0 == -CUDART_INF_F) ? 0.f : mn0;
        float mu1 = (mn1 == -CUDART_INF_F) ? 0.f : mn1;
        float al0 = ex2(mI0 - mu0), al1 = ex2(mI1 - mu1);
        float rs0 = 0.f, rs1 = 0.f;
        #pragma unroll
        for (int nt = 0; nt < 8; nt++) {
            s[nt][0] = ex2(s[nt][0] - mu0);
            s[nt][1] = ex2(s[nt][1] - mu0);
            s[nt][2] = ex2(s[nt][2] - mu1);
            s[nt][3] = ex2(s[nt][3] - mu1);
            rs0 += s[nt][0] + s[nt][1];
            rs1 += s[nt][2] + s[nt][3];
        }
        rs0 += __shfl_xor_sync(0xffffffffu, rs0, 1);
        rs0 += __shfl_xor_sync(0xffffffffu, rs0, 2);
        rs1 += __shfl_xor_sync(0xffffffffu, rs1, 1);
        rs1 += __shfl_xor_sync(0xffffffffu, rs1, 2);
        l0 = l0 * al0 + rs0; mI0 = mn0;
        l1 = l1 * al1 + rs1; mI1 = mn1;
        #pragma unroll
        for (int dt = 0; dt < 8; dt++) {
            o[dt][0] *= al0; o[dt][1] *= al0;
            o[dt][2] *= al1; o[dt][3] *= al1;
        }

        // ---- O += P V ----
        const uint32_t sVc = sVb + cur * HTILE_B;
        #pragma unroll
        for (int kp = 0; kp < 4; kp++) {
            uint32_t pa[4];
            pa[0] = packh2(s[2 * kp][0],     s[2 * kp][1]);
            pa[1] = packh2(s[2 * kp][2],     s[2 * kp][3]);
            pa[2] = packh2(s[2 * kp + 1][0], s[2 * kp + 1][1]);
            pa[3] = packh2(s[2 * kp + 1][2], s[2 * kp + 1][3]);
            #pragma unroll
            for (int np = 0; np < 4; np++) {
                uint32_t vf[4];
                ldm4t(vf, sVc + (16 * kp + v_row) * 144 + np * 32 + v_co);
                mma_f16(o[2 * np],     pa, vf[0], vf[1]);
                mma_f16(o[2 * np + 1], pa, vf[2], vf[3]);
            }
        }

        cp_wait0();
        __syncthreads();
    }

    // ---- epilogue ----
    float inv0 = 1.0f / fmaxf(l0, 1e-30f);
    float inv1 = 1.0f / fmaxf(l1, 1e-30f);
    const int h = bh & 15;
    const int row0 = s0 + 16 * w + r0;
    float* op0 = out + (size_t)(b * SEQ + row0) * HID + h * HD;
    float* op1 = out + (size_t)(b * SEQ + row0 + 8) * HID + h * HD;
    #pragma unroll
    for (int dt = 0; dt < 8; dt++) {
        int d = dt * 8 + q2;
        *(float2*)&op0[d] = make_float2(o[dt][0] * inv0, o[dt][1] * inv0);
        *(float2*)&op1[d] = make_float2(o[dt][2] * inv1, o[dt][3] * inv1);
    }
}

// ---------------------------------------------------------------------------
extern "C" void kernel_launch(void* const* d_in, const int* in_sizes, int n_in,
                              void* d_out, int out_size)
{
    const float* X    = (const float*)d_in[0];
    const int*   mask = (const int*)d_in[1];
    const float* Wq   = (const float*)d_in[2];
    const float* bq   = (const float*)d_in[3];
    const float* Wk   = (const float*)d_in[4];
    const float* bk   = (const float*)d_in[5];
    const float* Wv   = (const float*)d_in[6];
    const float* bv   = (const float*)d_in[7];
    float* out = (float*)d_out;

    cvt_kernel<<<592, 256>>>(X, Wq, Wk, Wv);

    cudaFuncSetAttribute(qkv_mma_kernel,
                         cudaFuncAttributeMaxDynamicSharedMemorySize, QKV_SMEM);
    qkv_mma_kernel<<<dim3(32, 8, 3), 256, QKV_SMEM>>>(bq, bk, bv);

    cudaFuncSetAttribute(attn_mma_kernel,
                         cudaFuncAttributeMaxDynamicSharedMemorySize, ATT_SMEM);
    attn_mma_kernel<<<dim3(SEQ / 64, BSZ * NH), 128, ATT_SMEM>>>(mask, out);
}

// round 15
// speedup vs baseline: 1.7503x; 1.0321x over previous
#include <cuda_runtime.h>
#include <cuda_fp16.h>
#include <math_constants.h>
#include <cstdint>

#define BSZ   2
#define SEQ   2048
#define HID   1024
#define NH    16
#define HD    64

// Scratch: projected Q/K/V as fp16 [b*NH+h][s][d]; fp16-preconverted X and W.
__device__ __half g_q[BSZ * NH * SEQ * HD];
__device__ __half g_k[BSZ * NH * SEQ * HD];
__device__ __half g_v[BSZ * NH * SEQ * HD];
__device__ __half g_xh[BSZ * SEQ * HID];
__device__ __half g_wh[3 * HID * HID];

// ============================================================================
// helpers
// ============================================================================
__device__ __forceinline__ uint32_t smem_u32(const void* p) {
    uint32_t a;
    asm("{ .reg .u64 t; cvta.to.shared.u64 t, %1; cvt.u32.u64 %0, t; }"
        : "=r"(a) : "l"(p));
    return a;
}
__device__ __forceinline__ void cp16(uint32_t s, const void* g) {
    asm volatile("cp.async.cg.shared.global [%0], [%1], 16;" :: "r"(s), "l"(g));
}
__device__ __forceinline__ void cp_commit() {
    asm volatile("cp.async.commit_group;" ::: "memory");
}
__device__ __forceinline__ void cp_wait1() {
    asm volatile("cp.async.wait_group 1;" ::: "memory");
}
__device__ __forceinline__ void cp_wait0() {
    asm volatile("cp.async.wait_group 0;" ::: "memory");
}
__device__ __forceinline__ float ex2(float x) {
    float r;
    asm("ex2.approx.f32 %0, %1;" : "=f"(r) : "f"(x));
    return r;
}
// packed fp16x2 exp2
__device__ __forceinline__ uint32_t ex2h2(uint32_t x) {
    uint32_t r;
    asm("ex2.approx.f16x2 %0, %1;" : "=r"(r) : "r"(x));
    return r;
}
// pack two fp32 into f16x2: lo half = first arg
__device__ __forceinline__ uint32_t packh2(float lo, float hi) {
    uint32_t d;
    asm("cvt.rn.f16x2.f32 %0, %1, %2;" : "=r"(d) : "f"(hi), "f"(lo));
    return d;
}
__device__ __forceinline__ void ldm4(uint32_t* r, uint32_t addr) {
    asm volatile("ldmatrix.sync.aligned.m8n8.x4.shared.b16 {%0,%1,%2,%3}, [%4];"
                 : "=r"(r[0]), "=r"(r[1]), "=r"(r[2]), "=r"(r[3]) : "r"(addr));
}
__device__ __forceinline__ void ldm4t(uint32_t* r, uint32_t addr) {
    asm volatile("ldmatrix.sync.aligned.m8n8.x4.trans.shared.b16 {%0,%1,%2,%3}, [%4];"
                 : "=r"(r[0]), "=r"(r[1]), "=r"(r[2]), "=r"(r[3]) : "r"(addr));
}
__device__ __forceinline__ void mma_f16(float* c, const uint32_t* a,
                                        uint32_t b0, uint32_t b1) {
    asm volatile(
        "mma.sync.aligned.m16n8k16.row.col.f32.f16.f16.f32 "
        "{%0,%1,%2,%3}, {%4,%5,%6,%7}, {%8,%9}, {%0,%1,%2,%3};"
        : "+f"(c[0]), "+f"(c[1]), "+f"(c[2]), "+f"(c[3])
        : "r"(a[0]), "r"(a[1]), "r"(a[2]), "r"(a[3]), "r"(b0), "r"(b1));
}

// ============================================================================
// Pre-pass: fp16-convert X and the three weight matrices.
// ============================================================================
__global__ __launch_bounds__(256) void cvt_kernel(
    const float* __restrict__ X,
    const float* __restrict__ Wq,
    const float* __restrict__ Wk,
    const float* __restrict__ Wv)
{
    const int tid    = blockIdx.x * blockDim.x + threadIdx.x;
    const int stride = gridDim.x * blockDim.x;
    const int NX = BSZ * SEQ * HID / 4;
    uint2* xh = (uint2*)g_xh;
    for (int i = tid; i < NX; i += stride) {
        float4 v = ((const float4*)X)[i];
        xh[i] = make_uint2(packh2(v.x, v.y), packh2(v.z, v.w));
    }
    const int NW = HID * HID / 4;
    uint2* wq = (uint2*)g_wh;
    uint2* wk = (uint2*)(g_wh + HID * HID);
    uint2* wv = (uint2*)(g_wh + 2 * HID * HID);
    for (int i = tid; i < NW; i += stride) {
        float4 a = ((const float4*)Wq)[i];
        wq[i] = make_uint2(packh2(a.x, a.y), packh2(a.z, a.w));
        float4 b = ((const float4*)Wk)[i];
        wk[i] = make_uint2(packh2(b.x, b.y), packh2(b.z, b.w));
        float4 c = ((const float4*)Wv)[i];
        wv[i] = make_uint2(packh2(c.x, c.y), packh2(c.z, c.w));
    }
}

// ============================================================================
// QKV projection, fp16 HMMA (exact R14): CTA tile 128x128, BK=64, m16n8k16,
// 3 physical stages / 2 loads in flight, one barrier per iteration.
// ============================================================================
#define QPITCH   72                           // halves per row (144B)
#define QA_BYTES (128 * QPITCH * 2)           // 18432
#define QSTAGE   (2 * QA_BYTES)               // 36864
#define QSTAGES  3
#define QKV_SMEM (QSTAGES * QSTAGE)           // 110592
#define QNKT     (HID / 64)                   // 16

__global__ __launch_bounds__(256) void qkv_mma_kernel(
    const float* __restrict__ bq,
    const float* __restrict__ bk,
    const float* __restrict__ bv)
{
    const float* bias; __half* out;
    if (blockIdx.z == 0)      { bias = bq; out = g_q; }
    else if (blockIdx.z == 1) { bias = bk; out = g_k; }
    else                      { bias = bv; out = g_v; }
    const __half* W = g_wh + (size_t)blockIdx.z * HID * HID;

    extern __shared__ char smem[];
    const uint32_t sb = smem_u32(smem);

    const int tid  = threadIdx.x;
    const int wid  = tid >> 5;
    const int lane = tid & 31;
    const int wm   = wid >> 1;
    const int wn   = wid & 1;
    const int m0   = blockIdx.x * 128;
    const int n0   = blockIdx.y * 128;

    const __half* gA0 = g_xh + (size_t)m0 * HID;
    const __half* gB0 = W + (size_t)n0 * HID;

    auto load_stage = [&](int stage, int kt) {
        const uint32_t sA = sb + stage * QSTAGE;
        const uint32_t sB = sA + QA_BYTES;
        const __half* gA = gA0 + kt * 64;
        const __half* gB = gB0 + kt * 64;
        #pragma unroll
        for (int i = 0; i < 4; i++) {
            int cid = tid + (i << 8);         // 0..1023
            int row = cid >> 3;               // 0..127
            int c   = cid & 7;                // 16B chunk in 128B row
            uint32_t off = row * 144 + c * 16;
            cp16(sA + off, gA + row * HID + c * 8);
            cp16(sB + off, gB + row * HID + c * 8);
        }
    };

    load_stage(0, 0); cp_commit();
    load_stage(1, 1); cp_commit();

    float acc[2][8][4];
    #pragma unroll
    for (int mt = 0; mt < 2; mt++)
        #pragma unroll
        for (int nt = 0; nt < 8; nt++)
            acc[mt][nt][0] = acc[mt][nt][1] = acc[mt][nt][2] = acc[mt][nt][3] = 0.f;

    const int a_row = lane & 15;
    const int a_co  = (lane >> 4) * 16;
    const int b_row = (lane & 7) + ((lane >> 4) << 3);
    const int b_co  = ((lane >> 3) & 1) * 16;

    for (int kt = 0; kt < QNKT; kt++) {
        cp_wait1();                           // load kt complete
        __syncthreads();                      // publish kt; stage (kt-1)%3 free
        if (kt + 2 < QNKT) {
            load_stage((kt + 2) % QSTAGES, kt + 2);
            cp_commit();
        }

        const uint32_t sA = sb + (kt % QSTAGES) * QSTAGE;
        const uint32_t sB = sA + QA_BYTES;

        #pragma unroll
        for (int kk = 0; kk < 4; kk++) {      // 4 x k16 = BK 64
            uint32_t af[2][4];
            #pragma unroll
            for (int mt = 0; mt < 2; mt++)
                ldm4(af[mt], sA + (wm * 32 + mt * 16 + a_row) * 144 + kk * 32 + a_co);
            #pragma unroll
            for (int np = 0; np < 4; np++) {
                uint32_t bf[4];
                ldm4(bf, sB + (wn * 64 + np * 16 + b_row) * 144 + kk * 32 + b_co);
                #pragma unroll
                for (int mt = 0; mt < 2; mt++) {
                    mma_f16(acc[mt][2 * np],     af[mt], bf[0], bf[1]);
                    mma_f16(acc[mt][2 * np + 1], af[mt], bf[2], bf[3]);
                }
            }
        }
    }

    const int n0g = n0 + wn * 64;
    const int h   = n0g >> 6;
    const int q2  = (lane & 3) * 2;
    #pragma unroll
    for (int mt = 0; mt < 2; mt++) {
        #pragma unroll
        for (int rh = 0; rh < 2; rh++) {
            int mrow = m0 + wm * 32 + mt * 16 + (lane >> 2) + rh * 8;
            int b = mrow >> 11;
            int s = mrow & (SEQ - 1);
            __half* op = out + (((size_t)(b * NH + h) * SEQ + s) * HD);
            #pragma unroll
            for (int nt = 0; nt < 8; nt++) {
                int d = nt * 8 + q2;
                float2 bb = *(const float2*)&bias[n0g + d];
                __half2 hv = __floats2half2_rn(acc[mt][nt][rh * 2 + 0] + bb.x,
                                               acc[mt][nt][rh * 2 + 1] + bb.y);
                *(__half2*)&op[d] = hv;
            }
        }
    }
}

// ============================================================================
// Flash attention v9: R12/R14 structure (64 q/CTA, 4 warps, occ 4) plus:
//  - P built via ex2.approx.f16x2 on packed (s - mu) pairs (half the MUFU ops)
//  - row sums l computed by an extra ones-column MMA (no FADD/shfl reduction)
// ============================================================================
#define HPITCH   72
#define HTILE_B  (64 * HPITCH * 2)            // 9216 bytes
#define NKT      (SEQ / 64)
#define ATT_SMEM (5 * HTILE_B + 512)
#define SCALE2   0.18033688f                  // 0.125 * log2(e)
#define ONES_H2  0x3C003C00u                  // (1.0h, 1.0h)

__global__ __launch_bounds__(128, 4) void attn_mma_kernel(
    const int* __restrict__ mask, float* __restrict__ out)
{
    extern __shared__ char smc[];
    const uint32_t sQ  = smem_u32(smc);
    const uint32_t sKb = sQ + HTILE_B;
    const uint32_t sVb = sQ + 3 * HTILE_B;
    const uint32_t sM  = sQ + 5 * HTILE_B;
    int* mskb = (int*)(smc + 5 * HTILE_B);

    const int tid  = threadIdx.x;
    const int lane = tid & 31;
    const int w    = tid >> 5;
    const int s0   = blockIdx.x * 64;
    const int bh   = blockIdx.y;
    const int b    = bh >> 4;

    const int q2 = (lane & 3) * 2;
    const int r0 = lane >> 2;

    const int a_row = lane & 15;
    const int a_co  = (lane >> 4) * 16;
    const int b_row = (lane & 7) + ((lane >> 4) << 3);
    const int b_co  = ((lane >> 3) & 1) * 16;
    const int v_row = lane & 15;
    const int v_co  = (lane >> 4) * 16;

    // ---- prologue ----
    {
        const __half* Qg = g_q + (size_t)(bh * SEQ + s0) * HD;
        const __half* Kg = g_k + (size_t)bh * SEQ * HD;
        const __half* Vg = g_v + (size_t)bh * SEQ * HD;
        #pragma unroll
        for (int i = 0; i < 4; i++) {
            int cid = tid + (i << 7);
            int row = cid >> 3;
            int c   = cid & 7;
            uint32_t off = row * 144 + c * 16;
            cp16(sQ  + off, Qg + row * HD + c * 8);
            cp16(sKb + off, Kg + row * HD + c * 8);
            cp16(sVb + off, Vg + row * HD + c * 8);
        }
        if (tid < 16) cp16(sM + tid * 16, mask + b * SEQ + tid * 4);
        cp_commit();
        cp_wait0();
    }
    __syncthreads();

    float mI0 = -CUDART_INF_F, mI1 = -CUDART_INF_F;
    float cl[4] = {0.f, 0.f, 0.f, 0.f};       // l accumulator (ones-column MMA)
    float o[8][4];
    #pragma unroll
    for (int dt = 0; dt < 8; dt++)
        o[dt][0] = o[dt][1] = o[dt][2] = o[dt][3] = 0.f;

    for (int kt = 0; kt < NKT; kt++) {
        const int cur = kt & 1;
        const bool has_next = (kt + 1 < NKT);

        if (has_next) {
            const __half* Kg = g_k + (size_t)(bh * SEQ + (kt + 1) * 64) * HD;
            const __half* Vg = g_v + (size_t)(bh * SEQ + (kt + 1) * 64) * HD;
            const uint32_t sKn = sKb + (cur ^ 1) * HTILE_B;
            const uint32_t sVn = sVb + (cur ^ 1) * HTILE_B;
            #pragma unroll
            for (int i = 0; i < 4; i++) {
                int cid = tid + (i << 7);
                int row = cid >> 3;
                int c   = cid & 7;
                uint32_t off = row * 144 + c * 16;
                cp16(sKn + off, Kg + row * HD + c * 8);
                cp16(sVn + off, Vg + row * HD + c * 8);
            }
            if (tid < 16)
                cp16(sM + (cur ^ 1) * 256 + tid * 16,
                     mask + b * SEQ + (kt + 1) * 64 + tid * 4);
            cp_commit();
        }

        // ---- S = Q K^T ----
        const uint32_t sKc = sKb + cur * HTILE_B;
        float s[8][4];
        #pragma unroll
        for (int nt = 0; nt < 8; nt++)
            s[nt][0] = s[nt][1] = s[nt][2] = s[nt][3] = 0.f;
        #pragma unroll
        for (int kk = 0; kk < 4; kk++) {
            uint32_t aq[4];
            ldm4(aq, sQ + (16 * w + a_row) * 144 + kk * 32 + a_co);
            #pragma unroll
            for (int np = 0; np < 4; np++) {
                uint32_t bf[4];
                ldm4(bf, sKc + (np * 16 + b_row) * 144 + kk * 32 + b_co);
                mma_f16(s[2 * np],     aq, bf[0], bf[1]);
                mma_f16(s[2 * np + 1], aq, bf[2], bf[3]);
            }
        }

        // ---- scale + mask + max (exp2 domain) ----
        const int* mk = mskb + cur * 64;
        float mx0 = -CUDART_INF_F, mx1 = -CUDART_INF_F;
        #pragma unroll
        for (int nt = 0; nt < 8; nt++) {
            float f0 = mk[nt * 8 + q2]     ? 0.f : -CUDART_INF_F;
            float f1 = mk[nt * 8 + q2 + 1] ? 0.f : -CUDART_INF_F;
            s[nt][0] = s[nt][0] * SCALE2 + f0;
            s[nt][1] = s[nt][1] * SCALE2 + f1;
            s[nt][2] = s[nt][2] * SCALE2 + f0;
            s[nt][3] = s[nt][3] * SCALE2 + f1;
            mx0 = fmaxf(mx0, fmaxf(s[nt][0], s[nt][1]));
            mx1 = fmaxf(mx1, fmaxf(s[nt][2], s[nt][3]));
        }
        mx0 = fmaxf(mx0, __shfl_xor_sync(0xffffffffu, mx0, 1));
        mx0 = fmaxf(mx0, __shfl_xor_sync(0xffffffffu, mx0, 2));
        mx1 = fmaxf(mx1, __shfl_xor_sync(0xffffffffu, mx1, 1));
        mx1 = fmaxf(mx1, __shfl_xor_sync(0xffffffffu, mx1, 2));

        float mn0 = fmaxf(mI0, mx0), mn1 = fmaxf(mI1, mx1);
        float mu0 = (mn0 == -CUDART_INF_F) ? 0.f : mn0;
        float mu1 = (mn1 == -CUDART_INF_F) ? 0.f : mn1;
        float al0 = ex2(mI0 - mu0), al1 = ex2(mI1 - mu1);
        mI0 = mn0; mI1 = mn1;

        // ---- P = exp2(s - mu) directly in fp16 pairs (A-fragments) ----
        uint32_t pp[8][2];
        #pragma unroll
        for (int nt = 0; nt < 8; nt++) {
            pp[nt][0] = ex2h2(packh2(s[nt][0] - mu0, s[nt][1] - mu0));
            pp[nt][1] = ex2h2(packh2(s[nt][2] - mu1, s[nt][3] - mu1));
        }

        // ---- rescale o and l by alpha ----
        #pragma unroll
        for (int dt = 0; dt < 8; dt++) {
            o[dt][0] *= al0; o[dt][1] *= al0;
            o[dt][2] *= al1; o[dt][3] *= al1;
        }
        cl[0] *= al0; cl[1] *= al0; cl[2] *= al1; cl[3] *= al1;

        // ---- O += P V ;  l += P * ones ----
        const uint32_t sVc = sVb + cur * HTILE_B;
        #pragma unroll
        for (int kp = 0; kp < 4; kp++) {
            uint32_t pk[4] = { pp[2 * kp][0], pp[2 * kp][1],
                               pp[2 * kp + 1][0], pp[2 * kp + 1][1] };
            mma_f16(cl, pk, ONES_H2, ONES_H2);
            #pragma unroll
            for (int np = 0; np < 4; np++) {
                uint32_t vf[4];
                ldm4t(vf, sVc + (16 * kp + v_row) * 144 + np * 32 + v_co);
                mma_f16(o[2 * np],     pk, vf[0], vf[1]);
                mma_f16(o[2 * np + 1], pk, vf[2], vf[3]);
            }
        }

        cp_wait0();
        __syncthreads();
    }

    // ---- epilogue ----
    float inv0 = 1.0f / fmaxf(cl[0], 1e-30f);
    float inv1 = 1.0f / fmaxf(cl[2], 1e-30f);
    const int h = bh & 15;
    const int row0 = s0 + 16 * w + r0;
    float* op0 = out + (size_t)(b * SEQ + row0) * HID + h * HD;
    float* op1 = out + (size_t)(b * SEQ + row0 + 8) * HID + h * HD;
    #pragma unroll
    for (int dt = 0; dt < 8; dt++) {
        int d = dt * 8 + q2;
        *(float2*)&op0[d] = make_float2(o[dt][0] * inv0, o[dt][1] * inv0);
        *(float2*)&op1[d] = make_float2(o[dt][2] * inv1, o[dt][3] * inv1);
    }
}

// ---------------------------------------------------------------------------
extern "C" void kernel_launch(void* const* d_in, const int* in_sizes, int n_in,
                              void* d_out, int out_size)
{
    const float* X    = (const float*)d_in[0];
    const int*   mask = (const int*)d_in[1];
    const float* Wq   = (const float*)d_in[2];
    const float* bq   = (const float*)d_in[3];
    const float* Wk   = (const float*)d_in[4];
    const float* bk   = (const float*)d_in[5];
    const float* Wv   = (const float*)d_in[6];
    const float* bv   = (const float*)d_in[7];
    float* out = (float*)d_out;

    cvt_kernel<<<592, 256>>>(X, Wq, Wk, Wv);

    cudaFuncSetAttribute(qkv_mma_kernel,
                         cudaFuncAttributeMaxDynamicSharedMemorySize, QKV_SMEM);
    qkv_mma_kernel<<<dim3(32, 8, 3), 256, QKV_SMEM>>>(bq, bk, bv);

    cudaFuncSetAttribute(attn_mma_kernel,
                         cudaFuncAttributeMaxDynamicSharedMemorySize, ATT_SMEM);
    attn_mma_kernel<<<dim3(SEQ / 64, BSZ * NH), 128, ATT_SMEM>>>(mask, out);
}